// round 1
// baseline (speedup 1.0000x reference)
#include <cuda_runtime.h>
#include <math.h>

// Problem constants
#define T_TOK 512
#define H_DIM 2048
#define E_NUM 64
#define TOPK  8
#define I_DIM 768

// ---------------- scratch (static device allocations; no cudaMalloc) ----------------
__device__ float g_act[T_TOK * TOPK * I_DIM];        // 12.6 MB  SwiGLU activations per (expert-grouped) slot
__device__ float g_partial[(size_t)T_TOK * TOPK * H_DIM]; // 33.5 MB per-(t,k) down-proj partials
__device__ float g_sact[T_TOK * I_DIM];              // 1.6 MB   shared-expert activations
__device__ int   g_counts[E_NUM];
__device__ int   g_offsets[E_NUM + 1];
__device__ int   g_cursor[E_NUM];
__device__ int   g_tki[T_TOK * TOPK];                // top-k expert idx per (t,k)
__device__ float g_tkw[T_TOK * TOPK];                // normalized weight per (t,k)
__device__ int   g_tok[T_TOK * TOPK];                // expert-grouped: token id per slot
__device__ int   g_dest[T_TOK * TOPK];               // expert-grouped: destination (t*8+k) per slot
__device__ float g_slotw[T_TOK * TOPK];              // expert-grouped: weight per slot

// ---------------- router ----------------
// One block per token, 64 threads (one per expert). Computes fp32 logits,
// sigmoid scores, bias-corrected top-8 selection, normalized weights, and
// per-expert counts.
__global__ void router_kernel(const float* __restrict__ x,
                              const float* __restrict__ gate_w,
                              const float* __restrict__ gate_b) {
    int t = blockIdx.x;
    __shared__ float sx[H_DIM];
    __shared__ float sscore[E_NUM];
    __shared__ float sbias[E_NUM];
    int tid = threadIdx.x;  // 0..63

    const float4* xr = (const float4*)(x + (size_t)t * H_DIM);
    float4* sx4 = (float4*)sx;
    for (int i = tid; i < H_DIM / 4; i += 64) sx4[i] = xr[i];
    __syncthreads();

    const float* w = gate_w + (size_t)tid * H_DIM;
    float acc = 0.f;
    #pragma unroll 4
    for (int h = 0; h < H_DIM; h += 4) {
        float4 wv = *(const float4*)(w + h);
        acc += wv.x * sx[h] + wv.y * sx[h + 1] + wv.z * sx[h + 2] + wv.w * sx[h + 3];
    }
    float score = 1.f / (1.f + expf(-acc));
    sscore[tid] = score;
    sbias[tid]  = score + gate_b[tid];
    __syncthreads();

    if (tid == 0) {
        int   idx[TOPK];
        float wts[TOPK];
        float sum = 0.f;
        for (int k = 0; k < TOPK; k++) {
            float best = -1e30f; int bi = 0;
            for (int e = 0; e < E_NUM; e++) {
                float v = sbias[e];
                if (v > best) { best = v; bi = e; }
            }
            sbias[bi] = -1e30f;
            idx[k] = bi;
            wts[k] = sscore[bi];
            sum += wts[k];
        }
        float inv = 1.f / (sum + 1e-20f);
        for (int k = 0; k < TOPK; k++) {
            g_tki[t * TOPK + k] = idx[k];
            g_tkw[t * TOPK + k] = wts[k] * inv;  // ROUTED_SCALING == 1
            atomicAdd(&g_counts[idx[k]], 1);
        }
    }
}

__global__ void zero_counts_kernel() { g_counts[threadIdx.x] = 0; }

__global__ void offsets_kernel() {
    int o = 0;
    for (int e = 0; e < E_NUM; e++) {
        g_offsets[e] = o;
        o += g_counts[e];
        g_cursor[e] = 0;
    }
    g_offsets[E_NUM] = o;
}

__global__ void scatter_kernel() {
    int i = blockIdx.x * blockDim.x + threadIdx.x;
    if (i >= T_TOK * TOPK) return;
    int e = g_tki[i];
    int pos = g_offsets[e] + atomicAdd(&g_cursor[e], 1);
    g_tok[pos]   = i / TOPK;
    g_dest[pos]  = i;
    g_slotw[pos] = g_tkw[i];
}

// ---------------- grouped dual-B GEMM + fused SiLU (gate & up share A) ----------------
// BM=64, BN=64, BK=16, 256 threads, 4x4 microtile, two accumulator sets.
// SHARED=false: blockIdx.z = expert; rows = expert-grouped token list.
// SHARED=true : rows = all 512 tokens (identity), writes g_sact.
template <bool SHARED>
__global__ void __launch_bounds__(256) gateup_kernel(
    const float* __restrict__ x,
    const float* __restrict__ w_gate_all,
    const float* __restrict__ w_up_all) {

    const int e = SHARED ? 0 : blockIdx.z;
    int base, nrows;
    if (SHARED) { base = 0; nrows = T_TOK; }
    else        { base = g_offsets[e]; nrows = g_offsets[e + 1] - base; }

    const int m0 = blockIdx.y * 64;
    if (m0 >= nrows) return;
    const int n0 = blockIdx.x * 64;

    const float* wg = SHARED ? w_gate_all : (w_gate_all + (size_t)e * H_DIM * I_DIM);
    const float* wu = SHARED ? w_up_all   : (w_up_all   + (size_t)e * H_DIM * I_DIM);

    __shared__ float As[16][68];  // padded, transposed A tile
    __shared__ float Bg[16][64];
    __shared__ float Bu[16][64];

    const int tid = threadIdx.x;
    const int tx = tid & 15;      // output col group
    const int ty = tid >> 4;      // output row group

    // A load: thread -> (row = tid/4, float4 at k-offset (tid%4)*4)
    const int ar = tid >> 2;
    const int ak = (tid & 3) * 4;
    const int arow = m0 + ar;
    const bool avalid = (arow < nrows);
    int tokid = 0;
    if (avalid) tokid = SHARED ? arow : g_tok[base + arow];
    const float* aptr = x + (size_t)tokid * H_DIM + ak;

    // B load: thread -> (k = tid/16, float4 at col (tid%16)*4)
    const int bk = tid >> 4;
    const int bc = (tid & 15) * 4;

    float accg[4][4] = {};
    float accu[4][4] = {};

    for (int k0 = 0; k0 < H_DIM; k0 += 16) {
        float4 av = make_float4(0.f, 0.f, 0.f, 0.f);
        if (avalid) av = *(const float4*)(aptr + k0);
        As[ak + 0][ar] = av.x;
        As[ak + 1][ar] = av.y;
        As[ak + 2][ar] = av.z;
        As[ak + 3][ar] = av.w;
        *(float4*)&Bg[bk][bc] = *(const float4*)(wg + (size_t)(k0 + bk) * I_DIM + n0 + bc);
        *(float4*)&Bu[bk][bc] = *(const float4*)(wu + (size_t)(k0 + bk) * I_DIM + n0 + bc);
        __syncthreads();

        #pragma unroll
        for (int kk = 0; kk < 16; kk++) {
            float4 a4 = *(const float4*)(&As[kk][ty * 4]);
            float4 g4 = *(const float4*)(&Bg[kk][tx * 4]);
            float4 u4 = *(const float4*)(&Bu[kk][tx * 4]);
            float a[4]  = {a4.x, a4.y, a4.z, a4.w};
            float bg[4] = {g4.x, g4.y, g4.z, g4.w};
            float bu[4] = {u4.x, u4.y, u4.z, u4.w};
            #pragma unroll
            for (int i2 = 0; i2 < 4; i2++) {
                #pragma unroll
                for (int j = 0; j < 4; j++) {
                    accg[i2][j] += a[i2] * bg[j];
                    accu[i2][j] += a[i2] * bu[j];
                }
            }
        }
        __syncthreads();
    }

    // Epilogue: act = silu(g) * u
    #pragma unroll
    for (int i2 = 0; i2 < 4; i2++) {
        int grow = m0 + ty * 4 + i2;
        if (grow >= nrows) continue;
        float* orow = SHARED ? (g_sact + (size_t)grow * I_DIM)
                             : (g_act  + (size_t)(base + grow) * I_DIM);
        #pragma unroll
        for (int j = 0; j < 4; j++) {
            float g = accg[i2][j];
            float u = accu[i2][j];
            float s = g / (1.f + expf(-g));
            orow[n0 + tx * 4 + j] = s * u;
        }
    }
}

// ---------------- grouped down-proj GEMM ----------------
// SHARED=false: A = g_act (expert-grouped slots), B = w_down[e], writes
//   weight-scaled rows to g_partial[dest]. Deterministic (fixed slot per (t,k)).
// SHARED=true : A = g_sact, B = sw_down, writes directly to d_out.
template <bool SHARED>
__global__ void __launch_bounds__(256) down_kernel(
    const float* __restrict__ w_down_all,
    float* __restrict__ out) {

    const int e = SHARED ? 0 : blockIdx.z;
    int base, nrows;
    if (SHARED) { base = 0; nrows = T_TOK; }
    else        { base = g_offsets[e]; nrows = g_offsets[e + 1] - base; }

    const int m0 = blockIdx.y * 64;
    if (m0 >= nrows) return;
    const int n0 = blockIdx.x * 64;

    const float* wd = SHARED ? w_down_all : (w_down_all + (size_t)e * I_DIM * H_DIM);
    const float* Asrc = SHARED ? g_sact : g_act;

    __shared__ float As[16][68];
    __shared__ float Bs[16][64];

    const int tid = threadIdx.x;
    const int tx = tid & 15;
    const int ty = tid >> 4;

    const int ar = tid >> 2;
    const int ak = (tid & 3) * 4;
    const int arow = m0 + ar;
    const bool avalid = (arow < nrows);
    const float* aptr = Asrc + (size_t)(base + (avalid ? arow : 0)) * I_DIM + ak;

    const int bk = tid >> 4;
    const int bc = (tid & 15) * 4;

    float acc[4][4] = {};

    for (int k0 = 0; k0 < I_DIM; k0 += 16) {
        float4 av = make_float4(0.f, 0.f, 0.f, 0.f);
        if (avalid) av = *(const float4*)(aptr + k0);
        As[ak + 0][ar] = av.x;
        As[ak + 1][ar] = av.y;
        As[ak + 2][ar] = av.z;
        As[ak + 3][ar] = av.w;
        *(float4*)&Bs[bk][bc] = *(const float4*)(wd + (size_t)(k0 + bk) * H_DIM + n0 + bc);
        __syncthreads();

        #pragma unroll
        for (int kk = 0; kk < 16; kk++) {
            float4 a4 = *(const float4*)(&As[kk][ty * 4]);
            float4 b4 = *(const float4*)(&Bs[kk][tx * 4]);
            float a[4] = {a4.x, a4.y, a4.z, a4.w};
            float b[4] = {b4.x, b4.y, b4.z, b4.w};
            #pragma unroll
            for (int i2 = 0; i2 < 4; i2++) {
                #pragma unroll
                for (int j = 0; j < 4; j++) acc[i2][j] += a[i2] * b[j];
            }
        }
        __syncthreads();
    }

    #pragma unroll
    for (int i2 = 0; i2 < 4; i2++) {
        int grow = m0 + ty * 4 + i2;
        if (grow >= nrows) continue;
        if (SHARED) {
            float* orow = out + (size_t)grow * H_DIM + n0;
            #pragma unroll
            for (int j = 0; j < 4; j++) orow[tx * 4 + j] = acc[i2][j];
        } else {
            int slot = base + grow;
            int dest = g_dest[slot];
            float w  = g_slotw[slot];
            float* orow = g_partial + (size_t)dest * H_DIM + n0;
            #pragma unroll
            for (int j = 0; j < 4; j++) orow[tx * 4 + j] = w * acc[i2][j];
        }
    }
}

// ---------------- combine: out = shared + sum_k partial[t,k,:] (fixed order, deterministic) ----------------
__global__ void combine_kernel(float* __restrict__ out) {
    int i = blockIdx.x * blockDim.x + threadIdx.x;  // over T*H
    int t = i / H_DIM;
    int h = i - t * H_DIM;
    float acc = out[i];  // shared-expert result already here
    #pragma unroll
    for (int k = 0; k < TOPK; k++)
        acc += g_partial[((size_t)t * TOPK + k) * H_DIM + h];
    out[i] = acc;
}

// ---------------- launch ----------------
extern "C" void kernel_launch(void* const* d_in, const int* in_sizes, int n_in,
                              void* d_out, int out_size) {
    const float* x       = (const float*)d_in[0];
    const float* gate_w  = (const float*)d_in[1];
    const float* gate_b  = (const float*)d_in[2];
    const float* w_gate  = (const float*)d_in[3];
    const float* w_up    = (const float*)d_in[4];
    const float* w_down  = (const float*)d_in[5];
    const float* sw_gate = (const float*)d_in[6];
    const float* sw_up   = (const float*)d_in[7];
    const float* sw_down = (const float*)d_in[8];
    float* out = (float*)d_out;

    zero_counts_kernel<<<1, 64>>>();
    router_kernel<<<T_TOK, 64>>>(x, gate_w, gate_b);
    offsets_kernel<<<1, 1>>>();
    scatter_kernel<<<(T_TOK * TOPK + 255) / 256, 256>>>();

    // Routed experts: gate/up fused SwiGLU (grid: I-tiles x row-tiles x experts)
    gateup_kernel<false><<<dim3(I_DIM / 64, 8, E_NUM), 256>>>(x, w_gate, w_up);
    // Shared expert gate/up
    gateup_kernel<true><<<dim3(I_DIM / 64, T_TOK / 64, 1), 256>>>(x, sw_gate, sw_up);
    // Routed down-proj -> per-(t,k) partials
    down_kernel<false><<<dim3(H_DIM / 64, 8, E_NUM), 256>>>(w_down, nullptr);
    // Shared down-proj -> writes d_out
    down_kernel<true><<<dim3(H_DIM / 64, T_TOK / 64, 1), 256>>>(sw_down, out);
    // Final combine
    combine_kernel<<<(T_TOK * H_DIM) / 256, 256>>>(out);
}

// round 2
// speedup vs baseline: 2.3714x; 2.3714x over previous
#include <cuda_runtime.h>
#include <cuda_bf16.h>
#include <math.h>
#include <stdint.h>

// Problem constants
#define T_TOK 512
#define H_DIM 2048
#define E_NUM 64
#define TOPK  8
#define I_DIM 768

// ---------------- scratch ----------------
__device__ float g_act[T_TOK * TOPK * I_DIM];
__device__ float g_partial[(size_t)T_TOK * TOPK * H_DIM];
__device__ float g_sact[T_TOK * I_DIM];
__device__ int   g_counts[E_NUM];
__device__ int   g_offsets[E_NUM + 1];
__device__ int   g_cursor[E_NUM];
__device__ int   g_tki[T_TOK * TOPK];
__device__ float g_tkw[T_TOK * TOPK];
__device__ int   g_tok[T_TOK * TOPK];
__device__ int   g_dest[T_TOK * TOPK];
__device__ float g_slotw[T_TOK * TOPK];

// ---------------- router ----------------
__global__ void router_kernel(const float* __restrict__ x,
                              const float* __restrict__ gate_w,
                              const float* __restrict__ gate_b) {
    int t = blockIdx.x;
    __shared__ float sx[H_DIM];
    __shared__ float sscore[E_NUM];
    __shared__ float sbias[E_NUM];
    int tid = threadIdx.x;  // 0..63

    const float4* xr = (const float4*)(x + (size_t)t * H_DIM);
    float4* sx4 = (float4*)sx;
    for (int i = tid; i < H_DIM / 4; i += 64) sx4[i] = xr[i];
    __syncthreads();

    const float* w = gate_w + (size_t)tid * H_DIM;
    float acc = 0.f;
    #pragma unroll 4
    for (int h = 0; h < H_DIM; h += 4) {
        float4 wv = *(const float4*)(w + h);
        acc += wv.x * sx[h] + wv.y * sx[h + 1] + wv.z * sx[h + 2] + wv.w * sx[h + 3];
    }
    float score = 1.f / (1.f + expf(-acc));
    sscore[tid] = score;
    sbias[tid]  = score + gate_b[tid];
    __syncthreads();

    if (tid == 0) {
        int   idx[TOPK];
        float wts[TOPK];
        float sum = 0.f;
        for (int k = 0; k < TOPK; k++) {
            float best = -1e30f; int bi = 0;
            for (int e = 0; e < E_NUM; e++) {
                float v = sbias[e];
                if (v > best) { best = v; bi = e; }
            }
            sbias[bi] = -1e30f;
            idx[k] = bi;
            wts[k] = sscore[bi];
            sum += wts[k];
        }
        float inv = 1.f / (sum + 1e-20f);
        for (int k = 0; k < TOPK; k++) {
            g_tki[t * TOPK + k] = idx[k];
            g_tkw[t * TOPK + k] = wts[k] * inv;
            atomicAdd(&g_counts[idx[k]], 1);
        }
    }
}

__global__ void zero_counts_kernel() { g_counts[threadIdx.x] = 0; }

__global__ void offsets_kernel() {
    int o = 0;
    for (int e = 0; e < E_NUM; e++) {
        g_offsets[e] = o;
        o += g_counts[e];
        g_cursor[e] = 0;
    }
    g_offsets[E_NUM] = o;
}

__global__ void scatter_kernel() {
    int i = blockIdx.x * blockDim.x + threadIdx.x;
    if (i >= T_TOK * TOPK) return;
    int e = g_tki[i];
    int pos = g_offsets[e] + atomicAdd(&g_cursor[e], 1);
    g_tok[pos]   = i / TOPK;
    g_dest[pos]  = i;
    g_slotw[pos] = g_tkw[i];
}

// ---------------- tensor-core helpers ----------------
__device__ __forceinline__ uint32_t smem_u32(const void* p) {
    return (uint32_t)__cvta_generic_to_shared(p);
}
__device__ __forceinline__ void ldsm4(uint32_t* r, uint32_t addr) {
    asm volatile("ldmatrix.sync.aligned.m8n8.x4.shared.b16 {%0,%1,%2,%3}, [%4];"
                 : "=r"(r[0]), "=r"(r[1]), "=r"(r[2]), "=r"(r[3]) : "r"(addr));
}
__device__ __forceinline__ void ldsm2t(uint32_t* r, uint32_t addr) {
    asm volatile("ldmatrix.sync.aligned.m8n8.x2.trans.shared.b16 {%0,%1}, [%2];"
                 : "=r"(r[0]), "=r"(r[1]) : "r"(addr));
}
__device__ __forceinline__ void mma16816(float* c, const uint32_t* a, const uint32_t* b) {
    asm volatile(
        "mma.sync.aligned.m16n8k16.row.col.f32.bf16.bf16.f32 "
        "{%0,%1,%2,%3}, {%4,%5,%6,%7}, {%8,%9}, {%0,%1,%2,%3};"
        : "+f"(c[0]), "+f"(c[1]), "+f"(c[2]), "+f"(c[3])
        : "r"(a[0]), "r"(a[1]), "r"(a[2]), "r"(a[3]), "r"(b[0]), "r"(b[1]));
}

// convert 8 floats -> bf16 hi/lo, store packed pairs (dst rows must be 4B aligned at j)
__device__ __forceinline__ void cvt8_store(const float4& va, const float4& vb,
                                           __nv_bfloat16* hrow, __nv_bfloat16* lrow) {
    float f[8] = {va.x, va.y, va.z, va.w, vb.x, vb.y, vb.z, vb.w};
    #pragma unroll
    for (int j = 0; j < 8; j += 2) {
        __nv_bfloat16 h0 = __float2bfloat16(f[j]);
        __nv_bfloat16 h1 = __float2bfloat16(f[j + 1]);
        __nv_bfloat16 l0 = __float2bfloat16(f[j]   - __bfloat162float(h0));
        __nv_bfloat16 l1 = __float2bfloat16(f[j+1] - __bfloat162float(h1));
        *(__nv_bfloat162*)(hrow + j) = __halves2bfloat162(h0, h1);
        *(__nv_bfloat162*)(lrow + j) = __halves2bfloat162(l0, l1);
    }
}

#define ASTRIDE 40  // bf16 elems per A smem row (64 rows)
#define BSTRIDE 72  // bf16 elems per B smem row (32 rows)

// ---------------- grouped dual-B GEMM + fused SiLU (tensor cores, split-bf16) ----------------
// BM=64, BN=64, BK=32. 256 threads = 8 warps in 2(M)x4(N); warp tile 32x16.
template <bool SHARED>
__global__ void __launch_bounds__(256) gateup_kernel(
    const float* __restrict__ x,
    const float* __restrict__ w_gate_all,
    const float* __restrict__ w_up_all) {

    const int e = SHARED ? 0 : blockIdx.z;
    int base, nrows;
    if (SHARED) { base = 0; nrows = T_TOK; }
    else        { base = g_offsets[e]; nrows = g_offsets[e + 1] - base; }

    const int m0 = blockIdx.y * 64;
    if (m0 >= nrows) return;
    const int n0 = blockIdx.x * 64;

    const float* wg = SHARED ? w_gate_all : (w_gate_all + (size_t)e * H_DIM * I_DIM);
    const float* wu = SHARED ? w_up_all   : (w_up_all   + (size_t)e * H_DIM * I_DIM);

    __shared__ __align__(16) __nv_bfloat16 Ah[64][ASTRIDE];
    __shared__ __align__(16) __nv_bfloat16 Al[64][ASTRIDE];
    __shared__ __align__(16) __nv_bfloat16 Bgh[32][BSTRIDE];
    __shared__ __align__(16) __nv_bfloat16 Bgl[32][BSTRIDE];
    __shared__ __align__(16) __nv_bfloat16 Buh[32][BSTRIDE];
    __shared__ __align__(16) __nv_bfloat16 Bul[32][BSTRIDE];

    const int tid = threadIdx.x;
    // A loader: row = tid/4, k-offset = (tid%4)*8  (8 floats)
    const int ar  = tid >> 2;
    const int akb = (tid & 3) * 8;
    const bool avalid = (m0 + ar < nrows);
    int tokid = 0;
    if (avalid) tokid = SHARED ? (m0 + ar) : g_tok[base + m0 + ar];
    const float* aptr = x + (size_t)tokid * H_DIM + akb;
    // B loader: k-row = tid/8, n-offset = (tid%8)*8
    const int bk = tid >> 3;
    const int bn = (tid & 7) * 8;
    const float* gptr = wg + (size_t)bk * I_DIM + n0 + bn;
    const float* uptr = wu + (size_t)bk * I_DIM + n0 + bn;

    const int wid  = tid >> 5;
    const int lane = tid & 31;
    const int wm = wid >> 2;   // 0..1
    const int wn = wid & 3;    // 0..3
    const int g  = lane >> 2;
    const int tg = lane & 3;

    float cg[2][2][4] = {};
    float cu[2][2][4] = {};

    const float4 z4 = make_float4(0.f, 0.f, 0.f, 0.f);
    float4 pa0, pa1, pg0, pg1, pu0, pu1;
    pa0 = avalid ? *(const float4*)(aptr)     : z4;
    pa1 = avalid ? *(const float4*)(aptr + 4) : z4;
    pg0 = *(const float4*)(gptr);
    pg1 = *(const float4*)(gptr + 4);
    pu0 = *(const float4*)(uptr);
    pu1 = *(const float4*)(uptr + 4);

    for (int k0 = 0; k0 < H_DIM; k0 += 32) {
        cvt8_store(pa0, pa1, &Ah[ar][akb], &Al[ar][akb]);
        cvt8_store(pg0, pg1, &Bgh[bk][bn], &Bgl[bk][bn]);
        cvt8_store(pu0, pu1, &Buh[bk][bn], &Bul[bk][bn]);
        __syncthreads();

        if (k0 + 32 < H_DIM) {
            int kn = k0 + 32;
            pa0 = avalid ? *(const float4*)(aptr + kn)     : z4;
            pa1 = avalid ? *(const float4*)(aptr + kn + 4) : z4;
            const float* gp = gptr + (size_t)kn * I_DIM;
            const float* up = uptr + (size_t)kn * I_DIM;
            pg0 = *(const float4*)(gp);
            pg1 = *(const float4*)(gp + 4);
            pu0 = *(const float4*)(up);
            pu1 = *(const float4*)(up + 4);
        }

        #pragma unroll
        for (int ks = 0; ks < 32; ks += 16) {
            uint32_t ah_f[2][4], al_f[2][4];
            #pragma unroll
            for (int mi = 0; mi < 2; mi++) {
                int row = wm * 32 + mi * 16 + (lane & 7) + (lane & 8);
                int col = ks + ((lane & 16) >> 1);
                ldsm4(ah_f[mi], smem_u32(&Ah[row][col]));
                ldsm4(al_f[mi], smem_u32(&Al[row][col]));
            }
            uint32_t bgh_f[2][2], bgl_f[2][2], buh_f[2][2], bul_f[2][2];
            #pragma unroll
            for (int ni = 0; ni < 2; ni++) {
                int brow = ks + (lane & 15);
                int bcol = wn * 16 + ni * 8;
                ldsm2t(bgh_f[ni], smem_u32(&Bgh[brow][bcol]));
                ldsm2t(bgl_f[ni], smem_u32(&Bgl[brow][bcol]));
                ldsm2t(buh_f[ni], smem_u32(&Buh[brow][bcol]));
                ldsm2t(bul_f[ni], smem_u32(&Bul[brow][bcol]));
            }
            #pragma unroll
            for (int mi = 0; mi < 2; mi++) {
                #pragma unroll
                for (int ni = 0; ni < 2; ni++) {
                    mma16816(cg[mi][ni], ah_f[mi], bgh_f[ni]);
                    mma16816(cg[mi][ni], ah_f[mi], bgl_f[ni]);
                    mma16816(cg[mi][ni], al_f[mi], bgh_f[ni]);
                    mma16816(cu[mi][ni], ah_f[mi], buh_f[ni]);
                    mma16816(cu[mi][ni], ah_f[mi], bul_f[ni]);
                    mma16816(cu[mi][ni], al_f[mi], buh_f[ni]);
                }
            }
        }
        __syncthreads();
    }

    // epilogue: silu(g)*u
    #pragma unroll
    for (int mi = 0; mi < 2; mi++) {
        int r0 = m0 + wm * 32 + mi * 16 + g;
        int r1 = r0 + 8;
        #pragma unroll
        for (int ni = 0; ni < 2; ni++) {
            int c0 = n0 + wn * 16 + ni * 8 + tg * 2;
            if (r0 < nrows) {
                float* orow = SHARED ? (g_sact + (size_t)r0 * I_DIM)
                                     : (g_act  + (size_t)(base + r0) * I_DIM);
                float g0 = cg[mi][ni][0], u0 = cu[mi][ni][0];
                float g1 = cg[mi][ni][1], u1 = cu[mi][ni][1];
                orow[c0]     = (g0 / (1.f + expf(-g0))) * u0;
                orow[c0 + 1] = (g1 / (1.f + expf(-g1))) * u1;
            }
            if (r1 < nrows) {
                float* orow = SHARED ? (g_sact + (size_t)r1 * I_DIM)
                                     : (g_act  + (size_t)(base + r1) * I_DIM);
                float g2 = cg[mi][ni][2], u2 = cu[mi][ni][2];
                float g3 = cg[mi][ni][3], u3 = cu[mi][ni][3];
                orow[c0]     = (g2 / (1.f + expf(-g2))) * u2;
                orow[c0 + 1] = (g3 / (1.f + expf(-g3))) * u3;
            }
        }
    }
}

// ---------------- grouped down-proj GEMM (tensor cores, split-bf16) ----------------
template <bool SHARED>
__global__ void __launch_bounds__(256) down_kernel(
    const float* __restrict__ w_down_all,
    float* __restrict__ out) {

    const int e = SHARED ? 0 : blockIdx.z;
    int base, nrows;
    if (SHARED) { base = 0; nrows = T_TOK; }
    else        { base = g_offsets[e]; nrows = g_offsets[e + 1] - base; }

    const int m0 = blockIdx.y * 64;
    if (m0 >= nrows) return;
    const int n0 = blockIdx.x * 64;

    const float* wd = SHARED ? w_down_all : (w_down_all + (size_t)e * I_DIM * H_DIM);
    const float* Asrc = SHARED ? g_sact : g_act;

    __shared__ __align__(16) __nv_bfloat16 Ah[64][ASTRIDE];
    __shared__ __align__(16) __nv_bfloat16 Al[64][ASTRIDE];
    __shared__ __align__(16) __nv_bfloat16 Bh[32][BSTRIDE];
    __shared__ __align__(16) __nv_bfloat16 Bl[32][BSTRIDE];

    const int tid = threadIdx.x;
    const int ar  = tid >> 2;
    const int akb = (tid & 3) * 8;
    const bool avalid = (m0 + ar < nrows);
    const float* aptr = Asrc + (size_t)(base + (avalid ? (m0 + ar) : 0)) * I_DIM + akb;

    const int bk = tid >> 3;
    const int bn = (tid & 7) * 8;
    const float* bptr = wd + (size_t)bk * H_DIM + n0 + bn;

    const int wid  = tid >> 5;
    const int lane = tid & 31;
    const int wm = wid >> 2;
    const int wn = wid & 3;
    const int g  = lane >> 2;
    const int tg = lane & 3;

    float acc[2][2][4] = {};

    const float4 z4 = make_float4(0.f, 0.f, 0.f, 0.f);
    float4 pa0, pa1, pb0, pb1;
    pa0 = avalid ? *(const float4*)(aptr)     : z4;
    pa1 = avalid ? *(const float4*)(aptr + 4) : z4;
    pb0 = *(const float4*)(bptr);
    pb1 = *(const float4*)(bptr + 4);

    for (int k0 = 0; k0 < I_DIM; k0 += 32) {
        cvt8_store(pa0, pa1, &Ah[ar][akb], &Al[ar][akb]);
        cvt8_store(pb0, pb1, &Bh[bk][bn], &Bl[bk][bn]);
        __syncthreads();

        if (k0 + 32 < I_DIM) {
            int kn = k0 + 32;
            pa0 = avalid ? *(const float4*)(aptr + kn)     : z4;
            pa1 = avalid ? *(const float4*)(aptr + kn + 4) : z4;
            const float* bp = bptr + (size_t)kn * H_DIM;
            pb0 = *(const float4*)(bp);
            pb1 = *(const float4*)(bp + 4);
        }

        #pragma unroll
        for (int ks = 0; ks < 32; ks += 16) {
            uint32_t ah_f[2][4], al_f[2][4];
            #pragma unroll
            for (int mi = 0; mi < 2; mi++) {
                int row = wm * 32 + mi * 16 + (lane & 7) + (lane & 8);
                int col = ks + ((lane & 16) >> 1);
                ldsm4(ah_f[mi], smem_u32(&Ah[row][col]));
                ldsm4(al_f[mi], smem_u32(&Al[row][col]));
            }
            uint32_t bh_f[2][2], bl_f[2][2];
            #pragma unroll
            for (int ni = 0; ni < 2; ni++) {
                int brow = ks + (lane & 15);
                int bcol = wn * 16 + ni * 8;
                ldsm2t(bh_f[ni], smem_u32(&Bh[brow][bcol]));
                ldsm2t(bl_f[ni], smem_u32(&Bl[brow][bcol]));
            }
            #pragma unroll
            for (int mi = 0; mi < 2; mi++) {
                #pragma unroll
                for (int ni = 0; ni < 2; ni++) {
                    mma16816(acc[mi][ni], ah_f[mi], bh_f[ni]);
                    mma16816(acc[mi][ni], ah_f[mi], bl_f[ni]);
                    mma16816(acc[mi][ni], al_f[mi], bh_f[ni]);
                }
            }
        }
        __syncthreads();
    }

    #pragma unroll
    for (int mi = 0; mi < 2; mi++) {
        int rr[2] = {m0 + wm * 32 + mi * 16 + g, m0 + wm * 32 + mi * 16 + g + 8};
        #pragma unroll
        for (int half = 0; half < 2; half++) {
            int r = rr[half];
            if (r >= nrows) continue;
            #pragma unroll
            for (int ni = 0; ni < 2; ni++) {
                int c0 = n0 + wn * 16 + ni * 8 + tg * 2;
                float v0 = acc[mi][ni][half * 2 + 0];
                float v1 = acc[mi][ni][half * 2 + 1];
                if (SHARED) {
                    float* orow = out + (size_t)r * H_DIM;
                    orow[c0]     = v0;
                    orow[c0 + 1] = v1;
                } else {
                    int slot = base + r;
                    int dest = g_dest[slot];
                    float w  = g_slotw[slot];
                    float* orow = g_partial + (size_t)dest * H_DIM;
                    orow[c0]     = w * v0;
                    orow[c0 + 1] = w * v1;
                }
            }
        }
    }
}

// ---------------- combine ----------------
__global__ void combine_kernel(float* __restrict__ out) {
    int i = blockIdx.x * blockDim.x + threadIdx.x;
    int t = i / H_DIM;
    int h = i - t * H_DIM;
    float acc = out[i];
    #pragma unroll
    for (int k = 0; k < TOPK; k++)
        acc += g_partial[((size_t)t * TOPK + k) * H_DIM + h];
    out[i] = acc;
}

// ---------------- launch ----------------
extern "C" void kernel_launch(void* const* d_in, const int* in_sizes, int n_in,
                              void* d_out, int out_size) {
    const float* x       = (const float*)d_in[0];
    const float* gate_w  = (const float*)d_in[1];
    const float* gate_b  = (const float*)d_in[2];
    const float* w_gate  = (const float*)d_in[3];
    const float* w_up    = (const float*)d_in[4];
    const float* w_down  = (const float*)d_in[5];
    const float* sw_gate = (const float*)d_in[6];
    const float* sw_up   = (const float*)d_in[7];
    const float* sw_down = (const float*)d_in[8];
    float* out = (float*)d_out;

    zero_counts_kernel<<<1, 64>>>();
    router_kernel<<<T_TOK, 64>>>(x, gate_w, gate_b);
    offsets_kernel<<<1, 1>>>();
    scatter_kernel<<<(T_TOK * TOPK + 255) / 256, 256>>>();

    gateup_kernel<false><<<dim3(I_DIM / 64, 8, E_NUM), 256>>>(x, w_gate, w_up);
    gateup_kernel<true><<<dim3(I_DIM / 64, T_TOK / 64, 1), 256>>>(x, sw_gate, sw_up);
    down_kernel<false><<<dim3(H_DIM / 64, 8, E_NUM), 256>>>(w_down, nullptr);
    down_kernel<true><<<dim3(H_DIM / 64, T_TOK / 64, 1), 256>>>(sw_down, out);
    combine_kernel<<<(T_TOK * H_DIM) / 256, 256>>>(out);
}